// round 7
// baseline (speedup 1.0000x reference)
#include <cuda_runtime.h>
#include <cuda_fp16.h>
#include <math.h>
#include <stdint.h>

// ---------------- problem constants ----------------
constexpr int B_   = 32768;
constexpr int ZD   = 64;
constexpr int XD   = 256;
constexpr int HID  = 512;
constexpr int T_   = 8;
constexpr int NB   = 8;
constexpr int MULT = 23;        // 3*NB-1
constexpr int O3   = 1472;      // ZD*MULT
constexpr int O3P  = 1536;      // padded to multiple of 128
constexpr int KCAT = 320;       // ZD + XD
#define TAILF 25.0f

// per-N-tile K bounds after degree-sorting the hidden units
__constant__ int c_k2tab[4]  = {128, 256, 384, 512};
__constant__ int c_k3tab[12] = {64, 128, 192, 192, 256, 320, 320, 384, 448, 448, 512, 512};

// ---------------- device scratch (static, allocation-free) ----------------
__device__ __align__(16) __half g_Wcat[T_ * HID * KCAT];
__device__ __align__(16) float  g_bcat[T_ * HID];
__device__ __align__(16) __half g_W2m[T_ * HID * HID];
__device__ __align__(16) float  g_b2p[T_ * HID];
__device__ __align__(16) __half g_W3m[(size_t)T_ * O3P * HID];
__device__ __align__(16) __half g_Acat[(size_t)B_ * KCAT];   // cols [0,64)=cur, [64,320)=x
__device__ __align__(16) __half g_h1[(size_t)B_ * HID];      // degree-sorted hidden order
__device__ __align__(16) __half g_h2[(size_t)B_ * HID];      // degree-sorted hidden order
__device__ __align__(16) __half g_p[(size_t)B_ * O3P];
__device__ float g_lad[B_];

__device__ __forceinline__ int hdeg(int j) { return j % (ZD - 1) + 1; } // 1..63
// inverse of the stable sort of hidden units by degree:
// degrees 1..8 have 9 units each (sorted pos 0..71), degrees 9..63 have 8 each.
__device__ __forceinline__ int origrow(int r) {
    return (r < 72) ? (r / 9) + 63 * (r % 9)
                    : (8 + (r - 72) / 8) + 63 * ((r - 72) % 8);
}

// ---------------- PTX helpers ----------------
__device__ __forceinline__ uint32_t smem_u32(const void* p) {
    uint32_t a;
    asm("{ .reg .u64 t; cvta.to.shared.u64 t, %1; cvt.u32.u64 %0, t; }" : "=r"(a) : "l"(p));
    return a;
}
__device__ __forceinline__ void cpasync16(uint32_t s, const void* g) {
    asm volatile("cp.async.cg.shared.global [%0], [%1], 16;" :: "r"(s), "l"(g));
}
__device__ __forceinline__ void cp_commit() {
    asm volatile("cp.async.commit_group;" ::: "memory");
}
template <int N>
__device__ __forceinline__ void cp_wait() {
    asm volatile("cp.async.wait_group %0;" :: "n"(N) : "memory");
}
__device__ __forceinline__ void ldsm4(uint32_t* r, uint32_t addr) {
    asm volatile("ldmatrix.sync.aligned.m8n8.x4.shared.b16 {%0,%1,%2,%3}, [%4];"
        : "=r"(r[0]), "=r"(r[1]), "=r"(r[2]), "=r"(r[3]) : "r"(addr));
}
// f16-accumulator MMA: {d0,d1} = A*B + {c0,c1}, all fp16 (half2-packed)
__device__ __forceinline__ void mma_f16acc(uint32_t* c, const uint32_t* a, uint32_t b0, uint32_t b1) {
    asm volatile("mma.sync.aligned.m16n8k16.row.col.f16.f16.f16.f16 "
        "{%0,%1}, {%2,%3,%4,%5}, {%6,%7}, {%0,%1};"
        : "+r"(c[0]), "+r"(c[1])
        : "r"(a[0]), "r"(a[1]), "r"(a[2]), "r"(a[3]), "r"(b0), "r"(b1));
}

// fast exp on the FMA pipe: rel err ~2e-7, valid |x| <= 80
__device__ __forceinline__ float fexp(float x) {
    x = fminf(fmaxf(x, -80.f), 80.f);
    float t = fmaf(x, 1.4426950408889634f, 12582912.0f);
    float i = t - 12582912.0f;
    float f = fmaf(x, 1.4426950408889634f, -i);
    float p = 1.3333558146e-3f;
    p = fmaf(p, f, 9.6181291076e-3f);
    p = fmaf(p, f, 5.5504108665e-2f);
    p = fmaf(p, f, 2.4022650696e-1f);
    p = fmaf(p, f, 6.9314718056e-1f);
    p = fmaf(p, f, 1.0f);
    return __int_as_float(__float_as_int(p) + ((int)i << 23));
}

// ---------------- weight prep (masking + degree-sort permutation, fp16) ----------------
__global__ void k_prep_wcat(const float* __restrict__ W1, const float* __restrict__ Wc,
                            const float* __restrict__ b1, const float* __restrict__ bc) {
    int i = blockIdx.x * blockDim.x + threadIdx.x;
    int total = T_ * HID * KCAT;
    if (i < total) {
        int k = i % KCAT;
        int r = (i / KCAT) % HID;     // sorted row
        int t = i / (KCAT * HID);
        int o = origrow(r);
        float v;
        if (k < ZD) {
            v = (hdeg(o) >= k + 1) ? W1[((size_t)t * HID + o) * ZD + k] : 0.f;
        } else {
            v = Wc[((size_t)t * HID + o) * XD + (k - ZD)];
        }
        g_Wcat[i] = __float2half_rn(v);
    }
    if (i < T_ * HID) {
        int r = i % HID, t = i / HID;
        int o = origrow(r);
        g_bcat[i] = b1[(size_t)t * HID + o] + bc[(size_t)t * HID + o];
    }
}

__global__ void k_prep_w2(const float* __restrict__ W2, const float* __restrict__ b2) {
    int i = blockIdx.x * blockDim.x + threadIdx.x;
    int total = T_ * HID * HID;
    if (i < total) {
        int c = i % HID;              // sorted col (input hidden)
        int r = (i / HID) % HID;      // sorted row (output hidden)
        int t = i / (HID * HID);
        int orow = origrow(r), ocol = origrow(c);
        float v = (hdeg(orow) >= hdeg(ocol))
                ? W2[((size_t)t * HID + orow) * HID + ocol] : 0.f;
        g_W2m[i] = __float2half_rn(v);
    }
    if (i < T_ * HID) {
        int r = i % HID, t = i / HID;
        g_b2p[i] = b2[(size_t)t * HID + origrow(r)];
    }
}

__global__ void k_prep_w3(const float* __restrict__ W3) {
    size_t i = (size_t)blockIdx.x * blockDim.x + threadIdx.x;
    size_t total = (size_t)T_ * O3P * HID;
    if (i >= total) return;
    int c = (int)(i % HID);           // sorted col
    int r = (int)((i / HID) % O3P);
    int t = (int)(i / ((size_t)HID * O3P));
    float v = 0.f;
    if (r < O3) {
        int od = r / MULT + 1;
        int ocol = origrow(c);
        if (od > hdeg(ocol)) v = W3[((size_t)t * O3 + r) * HID + ocol];
    }
    g_W3m[i] = __float2half_rn(v);
}

// ---------------- init ----------------
__global__ void k_init(const float* __restrict__ z, const float* __restrict__ x) {
    int i = blockIdx.x * blockDim.x + threadIdx.x;
    if (i < B_ * XD) {
        int b = i / XD, j = i % XD;
        g_Acat[(size_t)b * KCAT + ZD + j] = __float2half_rn(x[i]);
    }
    if (i < B_ * ZD) {
        int b = i / ZD, d = i % ZD;
        g_Acat[(size_t)b * KCAT + d] = __float2half_rn(z[i]);
    }
    if (i < B_) g_lad[i] = 0.f;
}

// ---------------- fp16 mma.sync NT GEMM, f16 chunk-accumulate + f32 promote ----------------
constexpr int STAGE_BYTES = 32768;               // 16KB A + 16KB B
constexpr int SMEM_BYTES  = 3 * STAGE_BYTES + 1024;

template <bool RELU, int TAB>
__global__ __launch_bounds__(128, 2)
void k_hgemm(const __half* __restrict__ A, const __half* __restrict__ W,
             const float* __restrict__ bias, __half* __restrict__ C,
             int K, int nvalid) {
    extern __shared__ char smraw[];
    const uint32_t base = (smem_u32(smraw) + 1023u) & ~1023u;

    const int tid  = threadIdx.x;
    const int warp = tid >> 5;
    const int lane = tid & 31;

    const int Krun = (TAB == 1) ? c_k2tab[blockIdx.x]
                   : (TAB == 2) ? c_k3tab[blockIdx.x] : K;
    const int KC = Krun >> 6;           // chunks of 64 halfs (128B/row)

    // ---- cp.async fill mapping ----
    const int trow = tid >> 3;          // 0..15
    const int c4   = tid & 7;           // 16B segment
    const uint32_t sfix = (uint32_t)((c4 ^ (trow & 7)) * 16);
    const size_t Kb = (size_t)K * 2;    // memory row stride (full K!)
    const char* Ag = (const char*)A + (size_t)(blockIdx.y * 128 + trow) * Kb + c4 * 16;
    const char* Wg = (const char*)W + (size_t)(blockIdx.x * 128 + trow) * Kb + c4 * 16;

    auto issue = [&](int chunk) {
        const uint32_t stA = base + (uint32_t)(chunk % 3) * STAGE_BYTES;
        const uint32_t stB = stA + 16384;
        const size_t go = (size_t)chunk * 128;   // bytes along K
#pragma unroll
        for (int i = 0; i < 8; i++) {
            uint32_t so = (uint32_t)(trow + 16 * i) * 128u + sfix;
            cpasync16(stA + so, Ag + (size_t)(16 * i) * Kb + go);
            cpasync16(stB + so, Wg + (size_t)(16 * i) * Kb + go);
        }
    };

    issue(0); cp_commit();
    if (KC > 1) issue(1);
    cp_commit();

    const int wm = (warp & 1) * 64;
    const int wn = (warp >> 1) * 64;
    const int lrow = lane & 15;
    const int lkh  = lane >> 4;

    float accf[4][8][4];
    uint32_t acc16[4][8][2];
#pragma unroll
    for (int mf = 0; mf < 4; mf++)
#pragma unroll
        for (int nf = 0; nf < 8; nf++) {
#pragma unroll
            for (int e = 0; e < 4; e++) accf[mf][nf][e] = 0.f;
            acc16[mf][nf][0] = 0u; acc16[mf][nf][1] = 0u;
        }

    for (int i = 0; i < KC; i++) {
        cp_wait<1>();
        __syncthreads();
        if (i + 2 < KC) issue(i + 2);
        cp_commit();

        const uint32_t stA = base + (uint32_t)(i % 3) * STAGE_BYTES;
        const uint32_t stB = stA + 16384;
#pragma unroll
        for (int ks = 0; ks < 4; ks++) {   // 4 x k16, f16 accumulate
            uint32_t a[4][4], b[4][4];
#pragma unroll
            for (int mf = 0; mf < 4; mf++) {
                int row = wm + mf * 16 + lrow;
                uint32_t seg = (uint32_t)((2 * ks + lkh) ^ (row & 7));
                ldsm4(a[mf], stA + (uint32_t)row * 128u + seg * 16u);
            }
#pragma unroll
            for (int p = 0; p < 4; p++) {
                int row = wn + p * 16 + lrow;
                uint32_t seg = (uint32_t)((2 * ks + lkh) ^ (row & 7));
                ldsm4(b[p], stB + (uint32_t)row * 128u + seg * 16u);
            }
#pragma unroll
            for (int mf = 0; mf < 4; mf++)
#pragma unroll
                for (int p = 0; p < 4; p++) {
                    mma_f16acc(acc16[mf][2 * p],     a[mf], b[p][0], b[p][2]);
                    mma_f16acc(acc16[mf][2 * p + 1], a[mf], b[p][1], b[p][3]);
                }
        }
        // promote f16 partials into f32 master every 2 chunks (128 K) and at end
        if ((i & 1) == 1 || i == KC - 1) {
#pragma unroll
            for (int mf = 0; mf < 4; mf++)
#pragma unroll
                for (int nf = 0; nf < 8; nf++) {
                    float2 lo = __half22float2(*(__half2*)&acc16[mf][nf][0]);
                    float2 hi = __half22float2(*(__half2*)&acc16[mf][nf][1]);
                    accf[mf][nf][0] += lo.x; accf[mf][nf][1] += lo.y;
                    accf[mf][nf][2] += hi.x; accf[mf][nf][3] += hi.y;
                    acc16[mf][nf][0] = 0u;   acc16[mf][nf][1] = 0u;
                }
        }
    }

    // ---- epilogue: regs -> gmem (half2 stores) ----
    const int N = gridDim.x * 128;
    const int gm0 = blockIdx.y * 128 + wm + (lane >> 2);
    const int gn0 = blockIdx.x * 128 + wn + (lane & 3) * 2;
#pragma unroll
    for (int nf = 0; nf < 8; nf++) {
        const int cc = gn0 + nf * 8;
        const float bv0 = (cc < nvalid) ? bias[cc] : 0.f;
        const float bv1 = (cc + 1 < nvalid) ? bias[cc + 1] : 0.f;
#pragma unroll
        for (int mf = 0; mf < 4; mf++) {
            const size_t r0 = (size_t)(gm0 + mf * 16);
            float v0 = accf[mf][nf][0] + bv0;
            float v1 = accf[mf][nf][1] + bv1;
            float v2 = accf[mf][nf][2] + bv0;
            float v3 = accf[mf][nf][3] + bv1;
            if (RELU) {
                v0 = fmaxf(v0, 0.f); v1 = fmaxf(v1, 0.f);
                v2 = fmaxf(v2, 0.f); v3 = fmaxf(v3, 0.f);
            }
            *(__half2*)(C + r0 * N + cc)       = __floats2half2_rn(v0, v1);
            *(__half2*)(C + (r0 + 8) * N + cc) = __floats2half2_rn(v2, v3);
        }
    }
}

// ---------------- RQ spline (elementwise over [B, ZD]) ----------------
__device__ __forceinline__ float softplus_f(float x) {
    return fmaxf(x, 0.f) + log1pf(fexp(-fabsf(x)));
}

__global__ void k_spline() {
    int b = blockIdx.x * 4 + threadIdx.y;
    int d = threadIdx.x;  // 0..63
    const __half* pp = g_p + (size_t)b * O3P + d * MULT;
    float z = __half2float(g_Acat[(size_t)b * KCAT + d]);

    const float ISH = 0.04419417382415922f;  // 1/sqrt(512)
    float uw[NB], uh[NB];
#pragma unroll
    for (int i = 0; i < NB; i++) {
        uw[i] = __half2float(pp[i]) * ISH;
        uh[i] = __half2float(pp[NB + i]) * ISH;
    }

    float cumw[NB + 1], cumh[NB + 1];
    {
        float mx = uw[0];
#pragma unroll
        for (int i = 1; i < NB; i++) mx = fmaxf(mx, uw[i]);
        float e[NB], s = 0.f;
#pragma unroll
        for (int i = 0; i < NB; i++) { e[i] = fexp(uw[i] - mx); s += e[i]; }
        float inv = __fdividef(1.f, s);
        const float fac = 1.f - NB * 0.001f;
        cumw[0] = -TAILF;
        float run = 0.f;
#pragma unroll
        for (int i = 0; i < NB; i++) {
            float w = 0.001f + fac * e[i] * inv;
            run += w;
            cumw[i + 1] = -TAILF + 2.f * TAILF * run;
        }
        cumw[NB] = TAILF;
    }
    {
        float mx = uh[0];
#pragma unroll
        for (int i = 1; i < NB; i++) mx = fmaxf(mx, uh[i]);
        float e[NB], s = 0.f;
#pragma unroll
        for (int i = 0; i < NB; i++) { e[i] = fexp(uh[i] - mx); s += e[i]; }
        float inv = __fdividef(1.f, s);
        const float fac = 1.f - NB * 0.001f;
        cumh[0] = -TAILF;
        float run = 0.f;
#pragma unroll
        for (int i = 0; i < NB; i++) {
            float h = 0.001f + fac * e[i] * inv;
            run += h;
            cumh[i + 1] = -TAILF + 2.f * TAILF * run;
        }
        cumh[NB] = TAILF;
    }

    float dv[NB + 1];
    dv[0] = 1.f;
    dv[NB] = 1.f;
#pragma unroll
    for (int k = 1; k < NB; k++) dv[k] = 0.001f + softplus_f(__half2float(pp[2 * NB + k - 1]));

    float zin = fminf(fmaxf(z, -TAILF), TAILF);
    int idx = 0;
#pragma unroll
    for (int i = 1; i <= NB; i++) {
        float edge = cumw[i] + (i == NB ? 1e-6f : 0.f);
        idx += (zin >= edge) ? 1 : 0;
    }
    if (idx > NB - 1) idx = NB - 1;

    float in_cw = 0.f, in_w = 1.f, in_ch = 0.f, in_h = 1.f, d0 = 1.f, d1 = 1.f;
#pragma unroll
    for (int i = 0; i < NB; i++) {
        if (idx == i) {
            in_cw = cumw[i]; in_w = cumw[i + 1] - cumw[i];
            in_ch = cumh[i]; in_h = cumh[i + 1] - cumh[i];
            d0 = dv[i]; d1 = dv[i + 1];
        }
    }

    float rw = __fdividef(1.f, in_w);
    float delta = in_h * rw;
    float th  = (zin - in_cw) * rw;
    float th1 = th * (1.f - th);
    float num = in_h * (delta * th * th + d0 * th1);
    float den = delta + (d0 + d1 - 2.f * delta) * th1;
    float outv = in_ch + __fdividef(num, den);
    float omt = 1.f - th;
    float dnum = delta * delta * (d1 * th * th + 2.f * delta * th1 + d0 * omt * omt);
    float ladv = __logf(dnum) - 2.f * __logf(den);

    bool inside = (z >= -TAILF) && (z <= TAILF);
    float newz = inside ? outv : z;
    ladv = inside ? ladv : 0.f;
    g_Acat[(size_t)b * KCAT + d] = __float2half_rn(newz);

#pragma unroll
    for (int off = 16; off; off >>= 1) ladv += __shfl_xor_sync(0xffffffffu, ladv, off);

    __shared__ float part[4][2];
    if ((d & 31) == 0) part[threadIdx.y][d >> 5] = ladv;
    __syncthreads();
    if (d == 0) g_lad[b] += part[threadIdx.y][0] + part[threadIdx.y][1];
}

// ---------------- final log-prob ----------------
__global__ void k_final(float* __restrict__ out) {
    int warp = threadIdx.x >> 5;
    int b = blockIdx.x * 8 + warp;
    int lane = threadIdx.x & 31;
    float c1 = __half2float(g_Acat[(size_t)b * KCAT + lane]);
    float c2 = __half2float(g_Acat[(size_t)b * KCAT + 32 + lane]);
    float s = c1 * c1 + c2 * c2;
#pragma unroll
    for (int off = 16; off; off >>= 1) s += __shfl_xor_sync(0xffffffffu, s, off);
    if (lane == 0) out[b] = -0.5f * s - 58.81206612510f + g_lad[b];
}

// ---------------- launch ----------------
extern "C" void kernel_launch(void* const* d_in, const int* in_sizes, int n_in,
                              void* d_out, int out_size) {
    const float* z  = (const float*)d_in[0];
    const float* x  = (const float*)d_in[1];
    const float* W1 = (const float*)d_in[2];
    const float* b1 = (const float*)d_in[3];
    const float* Wc = (const float*)d_in[4];
    const float* bc = (const float*)d_in[5];
    const float* W2 = (const float*)d_in[6];
    const float* b2 = (const float*)d_in[7];
    const float* W3 = (const float*)d_in[8];
    const float* b3 = (const float*)d_in[9];
    float* out = (float*)d_out;

    void *pWcat, *pBcat, *pW2m, *pB2p, *pW3m, *pAcat, *pH1, *pH2, *pP;
    cudaGetSymbolAddress(&pWcat, g_Wcat);
    cudaGetSymbolAddress(&pBcat, g_bcat);
    cudaGetSymbolAddress(&pW2m,  g_W2m);
    cudaGetSymbolAddress(&pB2p,  g_b2p);
    cudaGetSymbolAddress(&pW3m,  g_W3m);
    cudaGetSymbolAddress(&pAcat, g_Acat);
    cudaGetSymbolAddress(&pH1,   g_h1);
    cudaGetSymbolAddress(&pH2,   g_h2);
    cudaGetSymbolAddress(&pP,    g_p);

    const __half* Wcat = (const __half*)pWcat;
    const float*  Bcat = (const float*)pBcat;
    const __half* W2m  = (const __half*)pW2m;
    const float*  B2p  = (const float*)pB2p;
    const __half* W3m  = (const __half*)pW3m;
    const __half* Acat = (const __half*)pAcat;
    __half* H1 = (__half*)pH1;
    __half* H2 = (__half*)pH2;
    __half* P  = (__half*)pP;

    cudaFuncSetAttribute(k_hgemm<false, 0>, cudaFuncAttributeMaxDynamicSharedMemorySize, SMEM_BYTES);
    cudaFuncSetAttribute(k_hgemm<true, 1>,  cudaFuncAttributeMaxDynamicSharedMemorySize, SMEM_BYTES);
    cudaFuncSetAttribute(k_hgemm<false, 2>, cudaFuncAttributeMaxDynamicSharedMemorySize, SMEM_BYTES);

    // weight prep
    k_prep_wcat<<<(T_ * HID * KCAT + 255) / 256, 256>>>(W1, Wc, b1, bc);
    k_prep_w2<<<(T_ * HID * HID + 255) / 256, 256>>>(W2, b2);
    {
        size_t tot = (size_t)T_ * O3P * HID;
        k_prep_w3<<<(int)((tot + 255) / 256), 256>>>(W3);
    }
    k_init<<<(B_ * XD + 255) / 256, 256>>>(z, x);

    dim3 g1(HID / 128, B_ / 128);   // 4 x 256
    dim3 g3(O3P / 128, B_ / 128);   // 12 x 256

    for (int t = 0; t < T_; t++) {
        k_hgemm<false, 0><<<g1, 128, SMEM_BYTES>>>(Acat, Wcat + (size_t)t * HID * KCAT,
                                                   Bcat + t * HID, H1, KCAT, HID);
        k_hgemm<true, 1><<<g1, 128, SMEM_BYTES>>>(H1, W2m + (size_t)t * HID * HID,
                                                  B2p + t * HID, H2, HID, HID);
        k_hgemm<false, 2><<<g3, 128, SMEM_BYTES>>>(H2, W3m + (size_t)t * O3P * HID,
                                                   b3 + (size_t)t * O3, P, HID, O3);
        k_spline<<<B_ / 4, dim3(64, 4)>>>();
    }
    k_final<<<B_ / 8, 256>>>(out);
}

// round 8
// speedup vs baseline: 1.1080x; 1.1080x over previous
#include <cuda_runtime.h>
#include <cuda_fp16.h>
#include <math.h>
#include <stdint.h>

// ---------------- problem constants ----------------
constexpr int B_   = 32768;
constexpr int ZD   = 64;
constexpr int XD   = 256;
constexpr int HID  = 512;
constexpr int T_   = 8;
constexpr int NB   = 8;
constexpr int MULT = 23;        // 3*NB-1
constexpr int O3   = 1472;      // ZD*MULT
constexpr int O3Q  = 1536;      // 64 d * 24 (per-d padded layout)
constexpr int KCAT = 320;       // ZD + XD
constexpr int NDT  = 16;        // d-tiles in fused GEMM3 (4 d's each)
#define TAILF 25.0f

// per-N-tile K bounds after degree-sorting the hidden units
__constant__ int c_k2tab[4]  = {128, 256, 384, 512};
// fused GEMM3: tile j covers d in [4j,4j+4); K = ceil(count(hdeg <= 4j+3)/64)*64
__constant__ int c_k3b[NDT] = {64, 64, 128, 128, 192, 192, 256, 256,
                               320, 320, 384, 384, 448, 448, 512, 512};

// ---------------- device scratch (static, allocation-free) ----------------
__device__ __align__(16) __half g_Wcat[T_ * HID * KCAT];
__device__ __align__(16) float  g_bcat[T_ * HID];
__device__ __align__(16) __half g_W2m[T_ * HID * HID];
__device__ __align__(16) float  g_b2p[T_ * HID];
__device__ __align__(16) __half g_W3m[(size_t)T_ * O3Q * HID];   // per-d padded rows
__device__ __align__(16) float  g_b3p[T_ * O3Q];
__device__ __align__(16) __half g_Acat[(size_t)B_ * KCAT];   // cols [0,64)=cur, [64,320)=x
__device__ __align__(16) __half g_h1[(size_t)B_ * HID];      // degree-sorted hidden order
__device__ __align__(16) __half g_h2[(size_t)B_ * HID];      // degree-sorted hidden order
__device__ float g_ladp[NDT * B_];                           // per-d-tile lad partials

__device__ __forceinline__ int hdeg(int j) { return j % (ZD - 1) + 1; } // 1..63
// inverse of the stable sort of hidden units by degree
__device__ __forceinline__ int origrow(int r) {
    return (r < 72) ? (r / 9) + 63 * (r % 9)
                    : (8 + (r - 72) / 8) + 63 * ((r - 72) % 8);
}

// ---------------- PTX helpers ----------------
__device__ __forceinline__ uint32_t smem_u32(const void* p) {
    uint32_t a;
    asm("{ .reg .u64 t; cvta.to.shared.u64 t, %1; cvt.u32.u64 %0, t; }" : "=r"(a) : "l"(p));
    return a;
}
__device__ __forceinline__ void cpasync16(uint32_t s, const void* g) {
    asm volatile("cp.async.cg.shared.global [%0], [%1], 16;" :: "r"(s), "l"(g));
}
__device__ __forceinline__ void cp_commit() {
    asm volatile("cp.async.commit_group;" ::: "memory");
}
template <int N>
__device__ __forceinline__ void cp_wait() {
    asm volatile("cp.async.wait_group %0;" :: "n"(N) : "memory");
}
__device__ __forceinline__ void ldsm4(uint32_t* r, uint32_t addr) {
    asm volatile("ldmatrix.sync.aligned.m8n8.x4.shared.b16 {%0,%1,%2,%3}, [%4];"
        : "=r"(r[0]), "=r"(r[1]), "=r"(r[2]), "=r"(r[3]) : "r"(addr));
}
__device__ __forceinline__ void mma_f16(float* c, const uint32_t* a, uint32_t b0, uint32_t b1) {
    asm volatile("mma.sync.aligned.m16n8k16.row.col.f32.f16.f16.f32 "
        "{%0,%1,%2,%3}, {%4,%5,%6,%7}, {%8,%9}, {%0,%1,%2,%3};"
        : "+f"(c[0]), "+f"(c[1]), "+f"(c[2]), "+f"(c[3])
        : "r"(a[0]), "r"(a[1]), "r"(a[2]), "r"(a[3]), "r"(b0), "r"(b1));
}

// fast exp on the FMA pipe: rel err ~2e-7, valid |x| <= 80
__device__ __forceinline__ float fexp(float x) {
    x = fminf(fmaxf(x, -80.f), 80.f);
    float t = fmaf(x, 1.4426950408889634f, 12582912.0f);
    float i = t - 12582912.0f;
    float f = fmaf(x, 1.4426950408889634f, -i);
    float p = 1.3333558146e-3f;
    p = fmaf(p, f, 9.6181291076e-3f);
    p = fmaf(p, f, 5.5504108665e-2f);
    p = fmaf(p, f, 2.4022650696e-1f);
    p = fmaf(p, f, 6.9314718056e-1f);
    p = fmaf(p, f, 1.0f);
    return __int_as_float(__float_as_int(p) + ((int)i << 23));
}
__device__ __forceinline__ float softplus_f(float x) {
    return fmaxf(x, 0.f) + log1pf(fexp(-fabsf(x)));
}

// ---------------- weight prep ----------------
__global__ void k_prep_wcat(const float* __restrict__ W1, const float* __restrict__ Wc,
                            const float* __restrict__ b1, const float* __restrict__ bc) {
    int i = blockIdx.x * blockDim.x + threadIdx.x;
    int total = T_ * HID * KCAT;
    if (i < total) {
        int k = i % KCAT;
        int r = (i / KCAT) % HID;     // sorted row
        int t = i / (KCAT * HID);
        int o = origrow(r);
        float v;
        if (k < ZD) {
            v = (hdeg(o) >= k + 1) ? W1[((size_t)t * HID + o) * ZD + k] : 0.f;
        } else {
            v = Wc[((size_t)t * HID + o) * XD + (k - ZD)];
        }
        g_Wcat[i] = __float2half_rn(v);
    }
    if (i < T_ * HID) {
        int r = i % HID, t = i / HID;
        int o = origrow(r);
        g_bcat[i] = b1[(size_t)t * HID + o] + bc[(size_t)t * HID + o];
    }
}

__global__ void k_prep_w2(const float* __restrict__ W2, const float* __restrict__ b2) {
    int i = blockIdx.x * blockDim.x + threadIdx.x;
    int total = T_ * HID * HID;
    if (i < total) {
        int c = i % HID;              // sorted col
        int r = (i / HID) % HID;      // sorted row
        int t = i / (HID * HID);
        int orow = origrow(r), ocol = origrow(c);
        float v = (hdeg(orow) >= hdeg(ocol))
                ? W2[((size_t)t * HID + orow) * HID + ocol] : 0.f;
        g_W2m[i] = __float2half_rn(v);
    }
    if (i < T_ * HID) {
        int r = i % HID, t = i / HID;
        g_b2p[i] = b2[(size_t)t * HID + origrow(r)];
    }
}

// W3 with per-d padded rows: rp = d*24 + j; j<23 -> orig row d*23+j, j==23 -> zero
__global__ void k_prep_w3(const float* __restrict__ W3, const float* __restrict__ b3) {
    size_t i = (size_t)blockIdx.x * blockDim.x + threadIdx.x;
    size_t total = (size_t)T_ * O3Q * HID;
    if (i < total) {
        int c  = (int)(i % HID);          // sorted col
        int rp = (int)((i / HID) % O3Q);
        int t  = (int)(i / ((size_t)HID * O3Q));
        int d = rp / 24, j = rp % 24;
        float v = 0.f;
        if (j < 23) {
            int od = d + 1;
            int ocol = origrow(c);
            if (od > hdeg(ocol)) v = W3[((size_t)t * O3 + d * 23 + j) * HID + ocol];
        }
        g_W3m[i] = __float2half_rn(v);
    }
    if (i < (size_t)(T_ * O3Q)) {
        int rp = (int)(i % O3Q), t = (int)(i / O3Q);
        int d = rp / 24, j = rp % 24;
        g_b3p[i] = (j < 23) ? b3[(size_t)t * O3 + d * 23 + j] : 0.f;
    }
}

// ---------------- init ----------------
__global__ void k_init(const float* __restrict__ z, const float* __restrict__ x) {
    int i = blockIdx.x * blockDim.x + threadIdx.x;
    if (i < B_ * XD) {
        int b = i / XD, j = i % XD;
        g_Acat[(size_t)b * KCAT + ZD + j] = __float2half_rn(x[i]);
    }
    if (i < B_ * ZD) {
        int b = i / ZD, d = i % ZD;
        g_Acat[(size_t)b * KCAT + d] = __float2half_rn(z[i]);
    }
    if (i < NDT * B_) g_ladp[i] = 0.f;
}

// ---------------- fp16 mma.sync NT GEMM (GEMM1/GEMM2), f32 acc ----------------
constexpr int STAGE_BYTES = 32768;               // 16KB A + 16KB B
constexpr int SMEM_BYTES  = 3 * STAGE_BYTES + 1024;

template <bool RELU, int TAB>
__global__ __launch_bounds__(128, 2)
void k_hgemm(const __half* __restrict__ A, const __half* __restrict__ W,
             const float* __restrict__ bias, __half* __restrict__ C,
             int K, int nvalid) {
    extern __shared__ char smraw[];
    const uint32_t base = (smem_u32(smraw) + 1023u) & ~1023u;

    const int tid  = threadIdx.x;
    const int warp = tid >> 5;
    const int lane = tid & 31;

    const int Krun = (TAB == 1) ? c_k2tab[blockIdx.x] : K;
    const int KC = Krun >> 6;

    const int trow = tid >> 3;
    const int c4   = tid & 7;
    const uint32_t sfix = (uint32_t)((c4 ^ (trow & 7)) * 16);
    const size_t Kb = (size_t)K * 2;
    const char* Ag = (const char*)A + (size_t)(blockIdx.y * 128 + trow) * Kb + c4 * 16;
    const char* Wg = (const char*)W + (size_t)(blockIdx.x * 128 + trow) * Kb + c4 * 16;

    auto issue = [&](int chunk) {
        const uint32_t stA = base + (uint32_t)(chunk % 3) * STAGE_BYTES;
        const uint32_t stB = stA + 16384;
        const size_t go = (size_t)chunk * 128;
#pragma unroll
        for (int i = 0; i < 8; i++) {
            uint32_t so = (uint32_t)(trow + 16 * i) * 128u + sfix;
            cpasync16(stA + so, Ag + (size_t)(16 * i) * Kb + go);
            cpasync16(stB + so, Wg + (size_t)(16 * i) * Kb + go);
        }
    };

    issue(0); cp_commit();
    if (KC > 1) issue(1);
    cp_commit();

    const int wm = (warp & 1) * 64;
    const int wn = (warp >> 1) * 64;
    const int lrow = lane & 15;
    const int lkh  = lane >> 4;

    float acc[4][8][4];
#pragma unroll
    for (int mf = 0; mf < 4; mf++)
#pragma unroll
        for (int nf = 0; nf < 8; nf++)
#pragma unroll
            for (int e = 0; e < 4; e++) acc[mf][nf][e] = 0.f;

    for (int i = 0; i < KC; i++) {
        cp_wait<1>();
        __syncthreads();
        if (i + 2 < KC) issue(i + 2);
        cp_commit();

        const uint32_t stA = base + (uint32_t)(i % 3) * STAGE_BYTES;
        const uint32_t stB = stA + 16384;
#pragma unroll
        for (int ks = 0; ks < 4; ks++) {
            uint32_t a[4][4], b[4][4];
#pragma unroll
            for (int mf = 0; mf < 4; mf++) {
                int row = wm + mf * 16 + lrow;
                uint32_t seg = (uint32_t)((2 * ks + lkh) ^ (row & 7));
                ldsm4(a[mf], stA + (uint32_t)row * 128u + seg * 16u);
            }
#pragma unroll
            for (int p = 0; p < 4; p++) {
                int row = wn + p * 16 + lrow;
                uint32_t seg = (uint32_t)((2 * ks + lkh) ^ (row & 7));
                ldsm4(b[p], stB + (uint32_t)row * 128u + seg * 16u);
            }
#pragma unroll
            for (int mf = 0; mf < 4; mf++)
#pragma unroll
                for (int p = 0; p < 4; p++) {
                    mma_f16(acc[mf][2 * p],     a[mf], b[p][0], b[p][2]);
                    mma_f16(acc[mf][2 * p + 1], a[mf], b[p][1], b[p][3]);
                }
        }
    }

    const int N = gridDim.x * 128;
    const int gm0 = blockIdx.y * 128 + wm + (lane >> 2);
    const int gn0 = blockIdx.x * 128 + wn + (lane & 3) * 2;
#pragma unroll
    for (int nf = 0; nf < 8; nf++) {
        const int cc = gn0 + nf * 8;
        const float bv0 = (cc < nvalid) ? bias[cc] : 0.f;
        const float bv1 = (cc + 1 < nvalid) ? bias[cc + 1] : 0.f;
#pragma unroll
        for (int mf = 0; mf < 4; mf++) {
            const size_t r0 = (size_t)(gm0 + mf * 16);
            float v0 = acc[mf][nf][0] + bv0;
            float v1 = acc[mf][nf][1] + bv1;
            float v2 = acc[mf][nf][2] + bv0;
            float v3 = acc[mf][nf][3] + bv1;
            if (RELU) {
                v0 = fmaxf(v0, 0.f); v1 = fmaxf(v1, 0.f);
                v2 = fmaxf(v2, 0.f); v3 = fmaxf(v3, 0.f);
            }
            *(__half2*)(C + r0 * N + cc)       = __floats2half2_rn(v0, v1);
            *(__half2*)(C + (r0 + 8) * N + cc) = __floats2half2_rn(v2, v3);
        }
    }
}

// ---------------- fused GEMM3 + RQ-spline ----------------
// CTA tile 128x96 (= 4 complete d's). 4 warps as 2x2 (warp tile 64x48).
// Epilogue: acc+bias -> smem(stride 97) -> per-thread spline for 4 d's.
constexpr int G3_STAGE = 28672;                  // 16KB A + 12KB B (96 rows)
constexpr int G3_SMEM  = 3 * G3_STAGE + 1024;    // >= 128*97*4 epilogue buffer

__global__ __launch_bounds__(128, 2)
void k_g3spline(const __half* __restrict__ A, const __half* __restrict__ W,
                const float* __restrict__ bias, int dtile_unused) {
    extern __shared__ char smraw[];
    const uint32_t base = (smem_u32(smraw) + 1023u) & ~1023u;
    const uint32_t pad  = base - smem_u32(smraw);
    float* sp = (float*)(smraw + pad);           // epilogue view, stride 97

    const int tid  = threadIdx.x;
    const int warp = tid >> 5;
    const int lane = tid & 31;
    const int K = HID;

    const int Krun = c_k3b[blockIdx.x];
    const int KC = Krun >> 6;

    const int trow = tid >> 3;
    const int c4   = tid & 7;
    const uint32_t sfix = (uint32_t)((c4 ^ (trow & 7)) * 16);
    const size_t Kb = (size_t)K * 2;
    const char* Ag = (const char*)A + (size_t)(blockIdx.y * 128 + trow) * Kb + c4 * 16;
    const char* Wg = (const char*)W + (size_t)(blockIdx.x * 96 + trow) * Kb + c4 * 16;

    auto issue = [&](int chunk) {
        const uint32_t stA = base + (uint32_t)(chunk % 3) * G3_STAGE;
        const uint32_t stB = stA + 16384;
        const size_t go = (size_t)chunk * 128;
#pragma unroll
        for (int i = 0; i < 8; i++) {
            uint32_t so = (uint32_t)(trow + 16 * i) * 128u + sfix;
            cpasync16(stA + so, Ag + (size_t)(16 * i) * Kb + go);
            if (i < 6) cpasync16(stB + so, Wg + (size_t)(16 * i) * Kb + go);
        }
    };

    issue(0); cp_commit();
    if (KC > 1) issue(1);
    cp_commit();

    const int wm  = (warp & 1) * 64;
    const int wnl = (warp >> 1) * 48;
    const int lrow = lane & 15;
    const int lkh  = lane >> 4;

    float acc[4][6][4];
#pragma unroll
    for (int mf = 0; mf < 4; mf++)
#pragma unroll
        for (int nf = 0; nf < 6; nf++)
#pragma unroll
            for (int e = 0; e < 4; e++) acc[mf][nf][e] = 0.f;

    for (int i = 0; i < KC; i++) {
        cp_wait<1>();
        __syncthreads();
        if (i + 2 < KC) issue(i + 2);
        cp_commit();

        const uint32_t stA = base + (uint32_t)(i % 3) * G3_STAGE;
        const uint32_t stB = stA + 16384;
#pragma unroll
        for (int ks = 0; ks < 4; ks++) {
            uint32_t a[4][4], b[3][4];
#pragma unroll
            for (int mf = 0; mf < 4; mf++) {
                int row = wm + mf * 16 + lrow;
                uint32_t seg = (uint32_t)((2 * ks + lkh) ^ (row & 7));
                ldsm4(a[mf], stA + (uint32_t)row * 128u + seg * 16u);
            }
#pragma unroll
            for (int p = 0; p < 3; p++) {
                int row = wnl + p * 16 + lrow;
                uint32_t seg = (uint32_t)((2 * ks + lkh) ^ (row & 7));
                ldsm4(b[p], stB + (uint32_t)row * 128u + seg * 16u);
            }
#pragma unroll
            for (int mf = 0; mf < 4; mf++)
#pragma unroll
                for (int p = 0; p < 3; p++) {
                    mma_f16(acc[mf][2 * p],     a[mf], b[p][0], b[p][2]);
                    mma_f16(acc[mf][2 * p + 1], a[mf], b[p][1], b[p][3]);
                }
        }
    }

    // drain pending prefetches, then reuse stages as epilogue buffer
    cp_wait<0>();
    __syncthreads();

    // acc + bias -> smem [row][col], stride 97 floats
    {
        const int r0 = wm + (lane >> 2);
        const int c0 = wnl + (lane & 3) * 2;
        const int gb = blockIdx.x * 96;
#pragma unroll
        for (int nf = 0; nf < 6; nf++) {
            const int cc = c0 + nf * 8;
            const float bv0 = bias[gb + cc];
            const float bv1 = bias[gb + cc + 1];
#pragma unroll
            for (int mf = 0; mf < 4; mf++) {
                const int rr = r0 + mf * 16;
                sp[rr * 97 + cc]           = acc[mf][nf][0] + bv0;
                sp[rr * 97 + cc + 1]       = acc[mf][nf][1] + bv1;
                sp[(rr + 8) * 97 + cc]     = acc[mf][nf][2] + bv0;
                sp[(rr + 8) * 97 + cc + 1] = acc[mf][nf][3] + bv1;
            }
        }
    }
    __syncthreads();

    // per-thread spline: row = tid, d = 4*blockIdx.x + dl, params sp[tid*97 + 24*dl + j]
    const int bglob = blockIdx.y * 128 + tid;
    const float ISH = 0.04419417382415922f;  // 1/sqrt(512)
    float ladsum = 0.f;
#pragma unroll 1
    for (int dl = 0; dl < 4; dl++) {
        const int d = blockIdx.x * 4 + dl;
        const float* pp = sp + tid * 97 + dl * 24;
        float z = __half2float(g_Acat[(size_t)bglob * KCAT + d]);

        float cumw[NB + 1], cumh[NB + 1];
        {
            float mx = pp[0];
#pragma unroll
            for (int i = 1; i < NB; i++) mx = fmaxf(mx, pp[i]);
            float e[NB], s = 0.f;
#pragma unroll
            for (int i = 0; i < NB; i++) { e[i] = fexp((pp[i] - mx) * ISH); s += e[i]; }
            float inv = __fdividef(1.f, s);
            const float fac = 1.f - NB * 0.001f;
            cumw[0] = -TAILF;
            float run = 0.f;
#pragma unroll
            for (int i = 0; i < NB; i++) {
                run += 0.001f + fac * e[i] * inv;
                cumw[i + 1] = -TAILF + 2.f * TAILF * run;
            }
            cumw[NB] = TAILF;
        }
        {
            float mx = pp[NB];
#pragma unroll
            for (int i = 1; i < NB; i++) mx = fmaxf(mx, pp[NB + i]);
            float e[NB], s = 0.f;
#pragma unroll
            for (int i = 0; i < NB; i++) { e[i] = fexp((pp[NB + i] - mx) * ISH); s += e[i]; }
            float inv = __fdividef(1.f, s);
            const float fac = 1.f - NB * 0.001f;
            cumh[0] = -TAILF;
            float run = 0.f;
#pragma unroll
            for (int i = 0; i < NB; i++) {
                run += 0.001f + fac * e[i] * inv;
                cumh[i + 1] = -TAILF + 2.f * TAILF * run;
            }
            cumh[NB] = TAILF;
        }

        float dv[NB + 1];
        dv[0] = 1.f; dv[NB] = 1.f;
#pragma unroll
        for (int k = 1; k < NB; k++) dv[k] = 0.001f + softplus_f(pp[2 * NB + k - 1]);

        float zin = fminf(fmaxf(z, -TAILF), TAILF);
        int idx = 0;
#pragma unroll
        for (int i = 1; i <= NB; i++) {
            float edge = cumw[i] + (i == NB ? 1e-6f : 0.f);
            idx += (zin >= edge) ? 1 : 0;
        }
        if (idx > NB - 1) idx = NB - 1;

        float in_cw = 0.f, in_w = 1.f, in_ch = 0.f, in_h = 1.f, d0 = 1.f, d1 = 1.f;
#pragma unroll
        for (int i = 0; i < NB; i++) {
            if (idx == i) {
                in_cw = cumw[i]; in_w = cumw[i + 1] - cumw[i];
                in_ch = cumh[i]; in_h = cumh[i + 1] - cumh[i];
                d0 = dv[i]; d1 = dv[i + 1];
            }
        }

        float rw = __fdividef(1.f, in_w);
        float delta = in_h * rw;
        float th  = (zin - in_cw) * rw;
        float th1 = th * (1.f - th);
        float num = in_h * (delta * th * th + d0 * th1);
        float den = delta + (d0 + d1 - 2.f * delta) * th1;
        float outv = in_ch + __fdividef(num, den);
        float omt = 1.f - th;
        float dnum = delta * delta * (d1 * th * th + 2.f * delta * th1 + d0 * omt * omt);
        float lad = __logf(dnum) - 2.f * __logf(den);

        bool inside = (z >= -TAILF) && (z <= TAILF);
        float newz = inside ? outv : z;
        ladsum += inside ? lad : 0.f;
        g_Acat[(size_t)bglob * KCAT + d] = __float2half_rn(newz);
    }
    // per-(d-tile,b) partial; unique writer per step -> deterministic accumulate
    g_ladp[blockIdx.x * B_ + bglob] += ladsum;
}

// ---------------- final log-prob ----------------
__global__ void k_final(float* __restrict__ out) {
    int warp = threadIdx.x >> 5;
    int b = blockIdx.x * 8 + warp;
    int lane = threadIdx.x & 31;
    float c1 = __half2float(g_Acat[(size_t)b * KCAT + lane]);
    float c2 = __half2float(g_Acat[(size_t)b * KCAT + 32 + lane]);
    float v = -0.5f * (c1 * c1 + c2 * c2);
    if (lane < NDT) v += g_ladp[lane * B_ + b];
#pragma unroll
    for (int off = 16; off; off >>= 1) v += __shfl_xor_sync(0xffffffffu, v, off);
    if (lane == 0) out[b] = v - 58.81206612510f;
}

// ---------------- launch ----------------
extern "C" void kernel_launch(void* const* d_in, const int* in_sizes, int n_in,
                              void* d_out, int out_size) {
    const float* z  = (const float*)d_in[0];
    const float* x  = (const float*)d_in[1];
    const float* W1 = (const float*)d_in[2];
    const float* b1 = (const float*)d_in[3];
    const float* Wc = (const float*)d_in[4];
    const float* bc = (const float*)d_in[5];
    const float* W2 = (const float*)d_in[6];
    const float* b2 = (const float*)d_in[7];
    const float* W3 = (const float*)d_in[8];
    const float* b3 = (const float*)d_in[9];
    float* out = (float*)d_out;

    void *pWcat, *pBcat, *pW2m, *pB2p, *pW3m, *pB3p, *pAcat, *pH1, *pH2;
    cudaGetSymbolAddress(&pWcat, g_Wcat);
    cudaGetSymbolAddress(&pBcat, g_bcat);
    cudaGetSymbolAddress(&pW2m,  g_W2m);
    cudaGetSymbolAddress(&pB2p,  g_b2p);
    cudaGetSymbolAddress(&pW3m,  g_W3m);
    cudaGetSymbolAddress(&pB3p,  g_b3p);
    cudaGetSymbolAddress(&pAcat, g_Acat);
    cudaGetSymbolAddress(&pH1,   g_h1);
    cudaGetSymbolAddress(&pH2,   g_h2);

    const __half* Wcat = (const __half*)pWcat;
    const float*  Bcat = (const float*)pBcat;
    const __half* W2m  = (const __half*)pW2m;
    const float*  B2p  = (const float*)pB2p;
    const __half* W3m  = (const __half*)pW3m;
    const float*  B3p  = (const float*)pB3p;
    const __half* Acat = (const __half*)pAcat;
    __half* H1 = (__half*)pH1;
    __half* H2 = (__half*)pH2;

    cudaFuncSetAttribute(k_hgemm<false, 0>, cudaFuncAttributeMaxDynamicSharedMemorySize, SMEM_BYTES);
    cudaFuncSetAttribute(k_hgemm<true, 1>,  cudaFuncAttributeMaxDynamicSharedMemorySize, SMEM_BYTES);
    cudaFuncSetAttribute(k_g3spline,        cudaFuncAttributeMaxDynamicSharedMemorySize, G3_SMEM);

    k_prep_wcat<<<(T_ * HID * KCAT + 255) / 256, 256>>>(W1, Wc, b1, bc);
    k_prep_w2<<<(T_ * HID * HID + 255) / 256, 256>>>(W2, b2);
    {
        size_t tot = (size_t)T_ * O3Q * HID;
        k_prep_w3<<<(int)((tot + 255) / 256), 256>>>(W3, b3);
    }
    k_init<<<(B_ * XD + 255) / 256, 256>>>(z, x);

    dim3 g1(HID / 128, B_ / 128);   // 4 x 256
    dim3 g3(NDT, B_ / 128);         // 16 x 256

    for (int t = 0; t < T_; t++) {
        k_hgemm<false, 0><<<g1, 128, SMEM_BYTES>>>(Acat, Wcat + (size_t)t * HID * KCAT,
                                                   Bcat + t * HID, H1, KCAT, HID);
        k_hgemm<true, 1><<<g1, 128, SMEM_BYTES>>>(H1, W2m + (size_t)t * HID * HID,
                                                  B2p + t * HID, H2, HID, HID);
        k_g3spline<<<g3, 128, G3_SMEM>>>(H2, W3m + (size_t)t * O3Q * HID,
                                         B3p + (size_t)t * O3Q, 0);
    }
    k_final<<<B_ / 8, 256>>>(out);
}